// round 13
// baseline (speedup 1.0000x reference)
#include <cuda_runtime.h>
#include <cuda_bf16.h>
#include <cstdint>

// Problem constants (fixed by dataset)
#define NE 64      // experts
#define HH 2048    // hidden dim
#define FF 1408    // intermediate dim
#define MT 16      // tokens per expert
#define KT 64      // K tile (smem)
#define XSS 6      // ull stride per k-row (4 m-pairs + 2 pad, 48B, 16B-aligned)

typedef unsigned long long ull;

// Scratch for intermediate SwiGLU activations: [E][MT][FF] fp32 = 5.77 MB
__device__ float g_inter[(size_t)NE * MT * FF];

// ---------- packed fp32x2 helpers (ptxas never emits FFMA2 from C++) ----------
__device__ __forceinline__ ull fma2(ull a, ull b, ull c) {
    ull d;
    asm("fma.rn.f32x2 %0, %1, %2, %3;" : "=l"(d) : "l"(a), "l"(b), "l"(c));
    return d;
}
__device__ __forceinline__ ull pack2(float lo, float hi) {
    ull d;
    asm("mov.b64 %0, {%1, %2};" : "=l"(d) : "f"(lo), "f"(hi));
    return d;
}
__device__ __forceinline__ ull dup2(float v) {
    ull d;
    asm("mov.b64 %0, {%1, %1};" : "=l"(d) : "f"(v));
    return d;
}
__device__ __forceinline__ float2 unpk(ull v) {
    float lo, hi;
    asm("mov.b64 {%0, %1}, %2;" : "=f"(lo), "=f"(hi) : "l"(v));
    return make_float2(lo, hi);
}
__device__ __forceinline__ float silu(float g) {
    return g * (1.0f / (1.0f + __expf(-g)));
}

// ============================================================================
// Kernel A: inter[e,m,f] = silu(X_e @ gate_e)[m,f] * (X_e @ up_e)[m,f]
// Grid: (2*FF/128, NE) = (22, 64) = 1408 CTAs, block 128.
// blockIdx.x>>1 = f-block, blockIdx.x&1 = token half (m-split ACROSS CTAs;
// sibling CTAs are launch-adjacent so their weight streams share L2).
// Thread: 1 f-column x 8 tokens x {gate,up} — 8 f32x2 accumulators.
// R3-style pipeline: weights double-buffered in groups of 4 k; next x tile
// prefetched into registers across the whole compute phase.
// ============================================================================
__global__ __launch_bounds__(128, 8)
void moe_gate_up_kernel(const float* __restrict__ x,
                        const float* __restrict__ gate,
                        const float* __restrict__ up) {
    const int e   = blockIdx.y;
    const int hb  = blockIdx.x >> 1;      // f-block
    const int mz  = blockIdx.x & 1;       // token half (0: m 0..7, 1: m 8..15)
    const int tid = threadIdx.x;          // 0..127
    const int f   = hb * 128 + tid;
    const int kr  = tid & 63;             // k-row for fill
    const int ph  = tid >> 6;             // pair-half for fill

    __shared__ ull xs[KT * XSS];          // 64 k-rows x 4 m-pairs (+pad)

    ull ag[4], au[4];
#pragma unroll
    for (int j = 0; j < 4; j++) { ag[j] = 0; au[j] = 0; }

    const float* xb = x + ((size_t)e * MT + mz * 8) * HH;
    float xv[4];

    // ---- prologue: fill tile 0 (thread = k-row kr, pairs ph*2, ph*2+1) ----
#pragma unroll
    for (int i = 0; i < 2; i++) {
        int p = ph * 2 + i;
        xv[2 * i]     = xb[(size_t)(2 * p) * HH + kr];
        xv[2 * i + 1] = xb[(size_t)(2 * p + 1) * HH + kr];
    }
#pragma unroll
    for (int i = 0; i < 2; i++)
        xs[kr * XSS + ph * 2 + i] = pack2(xv[2 * i], xv[2 * i + 1]);
    __syncthreads();

    const float* gp0 = gate + (size_t)e * HH * FF + f;
    const float* up0 = up   + (size_t)e * HH * FF + f;

    for (int k0 = 0; k0 < HH; k0 += KT) {
        const bool has_next = (k0 + KT < HH);
        // prefetch next x tile into registers (in flight during compute)
        if (has_next) {
#pragma unroll
            for (int i = 0; i < 2; i++) {
                int p = ph * 2 + i;
                xv[2 * i]     = xb[(size_t)(2 * p) * HH + k0 + KT + kr];
                xv[2 * i + 1] = xb[(size_t)(2 * p + 1) * HH + k0 + KT + kr];
            }
        }

        const float* gp = gp0 + (size_t)k0 * FF;
        const float* uq = up0 + (size_t)k0 * FF;

        // double-buffered scalar weights, groups of 4 k
        float wg[2][4], wu[2][4];
#pragma unroll
        for (int j = 0; j < 4; j++) {
            wg[0][j] = gp[(size_t)j * FF];
            wu[0][j] = uq[(size_t)j * FF];
        }
#pragma unroll 2
        for (int kg = 0; kg < KT / 4; kg++) {
            const int cur = kg & 1, nxt = cur ^ 1;
            if (kg < KT / 4 - 1) {
#pragma unroll
                for (int j = 0; j < 4; j++) {
                    wg[nxt][j] = gp[(size_t)(4 * kg + 4 + j) * FF];
                    wu[nxt][j] = uq[(size_t)(4 * kg + 4 + j) * FF];
                }
            }
#pragma unroll
            for (int j = 0; j < 4; j++) {
                const int k = kg * 4 + j;
                ull g = dup2(wg[cur][j]);
                ull u = dup2(wu[cur][j]);
                const ulonglong2* xr = (const ulonglong2*)&xs[k * XSS];
                ulonglong2 xa = xr[0];   // m-pairs 0,1 (broadcast)
                ulonglong2 xc = xr[1];   // m-pairs 2,3
                ag[0] = fma2(xa.x, g, ag[0]); au[0] = fma2(xa.x, u, au[0]);
                ag[1] = fma2(xa.y, g, ag[1]); au[1] = fma2(xa.y, u, au[1]);
                ag[2] = fma2(xc.x, g, ag[2]); au[2] = fma2(xc.x, u, au[2]);
                ag[3] = fma2(xc.y, g, ag[3]); au[3] = fma2(xc.y, u, au[3]);
            }
        }
        __syncthreads();      // all reads of xs done
        if (has_next) {
#pragma unroll
            for (int i = 0; i < 2; i++)
                xs[kr * XSS + ph * 2 + i] = pack2(xv[2 * i], xv[2 * i + 1]);
        }
        __syncthreads();      // new tile visible
    }

    // ---- epilogue: SwiGLU + store (scalar per token row) ----
    float* dst = g_inter + ((size_t)e * MT + mz * 8) * FF + f;
#pragma unroll
    for (int p = 0; p < 4; p++) {
        float2 g = unpk(ag[p]);
        float2 u = unpk(au[p]);
        dst[(size_t)(2 * p) * FF]     = silu(g.x) * u.x;
        dst[(size_t)(2 * p + 1) * FF] = silu(g.y) * u.y;
    }
}

// ============================================================================
// Kernel B: out[e,m,h] = inter_e @ down_e
// Grid: (2*HH/128, NE) = (32, 64) = 2048 CTAs, block 128.
// Same across-CTA m-split; thread: 1 h-column x 8 tokens.
// ============================================================================
__global__ __launch_bounds__(128, 10)
void moe_down_kernel(const float* __restrict__ down,
                     float* __restrict__ out) {
    const int e   = blockIdx.y;
    const int hb  = blockIdx.x >> 1;
    const int mz  = blockIdx.x & 1;
    const int tid = threadIdx.x;
    const int h   = hb * 128 + tid;
    const int kr  = tid & 63;
    const int ph  = tid >> 6;

    __shared__ ull xs[KT * XSS];

    ull acc[4];
#pragma unroll
    for (int j = 0; j < 4; j++) acc[j] = 0;

    const float* ib = g_inter + ((size_t)e * MT + mz * 8) * FF;
    float xv[4];

#pragma unroll
    for (int i = 0; i < 2; i++) {
        int p = ph * 2 + i;
        xv[2 * i]     = ib[(size_t)(2 * p) * FF + kr];
        xv[2 * i + 1] = ib[(size_t)(2 * p + 1) * FF + kr];
    }
#pragma unroll
    for (int i = 0; i < 2; i++)
        xs[kr * XSS + ph * 2 + i] = pack2(xv[2 * i], xv[2 * i + 1]);
    __syncthreads();

    const float* dp0 = down + (size_t)e * FF * HH + h;

    for (int k0 = 0; k0 < FF; k0 += KT) {
        const bool has_next = (k0 + KT < FF);
        if (has_next) {
#pragma unroll
            for (int i = 0; i < 2; i++) {
                int p = ph * 2 + i;
                xv[2 * i]     = ib[(size_t)(2 * p) * FF + k0 + KT + kr];
                xv[2 * i + 1] = ib[(size_t)(2 * p + 1) * FF + k0 + KT + kr];
            }
        }

        const float* dp = dp0 + (size_t)k0 * HH;

        // double-buffered scalar weights, groups of 4 k
        float wd[2][4];
#pragma unroll
        for (int j = 0; j < 4; j++)
            wd[0][j] = dp[(size_t)j * HH];
#pragma unroll 4
        for (int kg = 0; kg < KT / 4; kg++) {
            const int cur = kg & 1, nxt = cur ^ 1;
            if (kg < KT / 4 - 1) {
#pragma unroll
                for (int j = 0; j < 4; j++)
                    wd[nxt][j] = dp[(size_t)(4 * kg + 4 + j) * HH];
            }
#pragma unroll
            for (int j = 0; j < 4; j++) {
                const int k = kg * 4 + j;
                ull w = dup2(wd[cur][j]);
                const ulonglong2* xr = (const ulonglong2*)&xs[k * XSS];
                ulonglong2 xa = xr[0];
                ulonglong2 xc = xr[1];
                acc[0] = fma2(xa.x, w, acc[0]);
                acc[1] = fma2(xa.y, w, acc[1]);
                acc[2] = fma2(xc.x, w, acc[2]);
                acc[3] = fma2(xc.y, w, acc[3]);
            }
        }
        __syncthreads();
        if (has_next) {
#pragma unroll
            for (int i = 0; i < 2; i++)
                xs[kr * XSS + ph * 2 + i] = pack2(xv[2 * i], xv[2 * i + 1]);
        }
        __syncthreads();
    }

    float* ob = out + ((size_t)e * MT + mz * 8) * HH + h;
#pragma unroll
    for (int p = 0; p < 4; p++) {
        float2 v = unpk(acc[p]);
        ob[(size_t)(2 * p) * HH]     = v.x;
        ob[(size_t)(2 * p + 1) * HH] = v.y;
    }
}

// ============================================================================
// Launch
// Inputs (metadata order):
//   d_in[0] = permuted_local_hidden_states [T=1024, H=2048] f32
//   d_in[1] = gate_proj [E, H, F] f32
//   d_in[2] = up_proj   [E, H, F] f32
//   d_in[3] = down_proj [E, F, H] f32
//   d_in[4] = tokens_per_expert [E] i32  (uniform 16 — unused)
// Output: [T, H] f32
// ============================================================================
extern "C" void kernel_launch(void* const* d_in, const int* in_sizes, int n_in,
                              void* d_out, int out_size) {
    const float* x    = (const float*)d_in[0];
    const float* gate = (const float*)d_in[1];
    const float* up   = (const float*)d_in[2];
    const float* down = (const float*)d_in[3];
    float* out = (float*)d_out;

    dim3 gridA(2 * FF / 128, NE);   // (22, 64) = 1408 CTAs x 4 warps
    moe_gate_up_kernel<<<gridA, 128>>>(x, gate, up);

    dim3 gridB(2 * HH / 128, NE);   // (32, 64) = 2048 CTAs x 4 warps
    moe_down_kernel<<<gridB, 128>>>(down, out);
}

// round 14
// speedup vs baseline: 1.3902x; 1.3902x over previous
#include <cuda_runtime.h>
#include <cuda_bf16.h>
#include <cstdint>

// Problem constants (fixed by dataset)
#define NE 64      // experts
#define HH 2048    // hidden dim
#define FF 1408    // intermediate dim
#define MT 16      // tokens per expert
#define KT 64      // K tile (smem)
#define XSS 10     // ull stride per k-row in x tile (8 m-pairs + 2 pad)

typedef unsigned long long ull;

// Scratch:
//  g_part[w][z]  : partial (X@W) sums, w in {gate,up}, z = k-half  (4 x 5.77 MB)
//  g_inter       : fused SwiGLU activations                        (5.77 MB)
//  g_opart[z]    : partial down-proj sums, z = k-half              (2 x 8.4 MB)
__device__ float g_part[4][(size_t)NE * MT * FF];
__device__ float g_inter[(size_t)NE * MT * FF];
__device__ float g_opart[2][(size_t)NE * MT * HH];

// ---------- packed fp32x2 helpers (ptxas never emits FFMA2 from C++) ----------
__device__ __forceinline__ ull fma2(ull a, ull b, ull c) {
    ull d;
    asm("fma.rn.f32x2 %0, %1, %2, %3;" : "=l"(d) : "l"(a), "l"(b), "l"(c));
    return d;
}
__device__ __forceinline__ ull pack2(float lo, float hi) {
    ull d;
    asm("mov.b64 %0, {%1, %2};" : "=l"(d) : "f"(lo), "f"(hi));
    return d;
}
__device__ __forceinline__ ull dup2(float v) {
    ull d;
    asm("mov.b64 %0, {%1, %1};" : "=l"(d) : "f"(v));
    return d;
}
__device__ __forceinline__ float2 unpk(ull v) {
    float lo, hi;
    asm("mov.b64 {%0, %1}, %2;" : "=f"(lo), "=f"(hi) : "l"(v));
    return make_float2(lo, hi);
}
__device__ __forceinline__ float silu(float g) {
    return g * (1.0f / (1.0f + __expf(-g)));
}

// ============================================================================
// K1 proj: partial[w][zk][e,m,f] = X_e[:, kr] @ W_e[kr, f],  kr = zk-th half
// Grid: (FF/128, NE, 4); z&1 = k-half, z>>1 = matrix (0 gate, 1 up).
// Block 128. Thread: 2 f-columns x 8 tokens (m-half by tid>>6), 8 f32x2 accs.
// Pipeline = proven R3-B: weight dbuf in groups of 4 k (LDG.64), x tile
// register-prefetched across compute. 2816 CTAs -> 8/SM resident, 32 warps.
// ============================================================================
__global__ __launch_bounds__(128, 8)
void moe_proj_kernel(const float* __restrict__ x,
                     const float* __restrict__ gate,
                     const float* __restrict__ up) {
    const int e   = blockIdx.y;
    const int z   = blockIdx.z;
    const int zk  = z & 1;                // k-half: [zk*1024, zk*1024+1024)
    const int wm  = z >> 1;               // 0: gate, 1: up
    const int tid = threadIdx.x;
    const int lf  = tid & 63;
    const int mh  = tid >> 6;
    const int f   = blockIdx.x * 128 + lf * 2;
    const int KH  = HH / 2;               // 1024

    const float* W = wm ? up : gate;

    __shared__ ull xs[KT * XSS];

    ull a0[4], a1[4];
#pragma unroll
    for (int j = 0; j < 4; j++) { a0[j] = 0; a1[j] = 0; }

    const float* xb = x + (size_t)e * MT * HH + (size_t)zk * KH;
    float xv[8];

    // ---- prologue: fill tile 0 ----
#pragma unroll
    for (int i = 0; i < 4; i++) {
        int m0 = (mh * 4 + i) * 2;
        xv[2 * i]     = xb[(size_t)m0 * HH + lf];
        xv[2 * i + 1] = xb[(size_t)(m0 + 1) * HH + lf];
    }
#pragma unroll
    for (int i = 0; i < 4; i++)
        xs[lf * XSS + mh * 4 + i] = pack2(xv[2 * i], xv[2 * i + 1]);
    __syncthreads();

    const float* wp0 = W + ((size_t)e * HH + zk * KH) * FF + f;

    for (int k0 = 0; k0 < KH; k0 += KT) {
        const bool has_next = (k0 + KT < KH);
        if (has_next) {
#pragma unroll
            for (int i = 0; i < 4; i++) {
                int m0 = (mh * 4 + i) * 2;
                xv[2 * i]     = xb[(size_t)m0 * HH + k0 + KT + lf];
                xv[2 * i + 1] = xb[(size_t)(m0 + 1) * HH + k0 + KT + lf];
            }
        }

        const float* wp = wp0 + (size_t)k0 * FF;

        // double-buffered weights, groups of 4 k (LDG.64)
        float2 wv[2][4];
#pragma unroll
        for (int j = 0; j < 4; j++)
            wv[0][j] = *(const float2*)(wp + (size_t)j * FF);
#pragma unroll 4
        for (int kg = 0; kg < KT / 4; kg++) {
            const int cur = kg & 1, nxt = cur ^ 1;
            if (kg < KT / 4 - 1) {
#pragma unroll
                for (int j = 0; j < 4; j++)
                    wv[nxt][j] = *(const float2*)(wp + (size_t)(4 * kg + 4 + j) * FF);
            }
#pragma unroll
            for (int j = 0; j < 4; j++) {
                const int k = kg * 4 + j;
                ull w0 = dup2(wv[cur][j].x), w1 = dup2(wv[cur][j].y);
                const ulonglong2* xr = (const ulonglong2*)&xs[k * XSS + mh * 4];
                ulonglong2 xa = xr[0];
                ulonglong2 xc = xr[1];
                a0[0] = fma2(xa.x, w0, a0[0]); a1[0] = fma2(xa.x, w1, a1[0]);
                a0[1] = fma2(xa.y, w0, a0[1]); a1[1] = fma2(xa.y, w1, a1[1]);
                a0[2] = fma2(xc.x, w0, a0[2]); a1[2] = fma2(xc.x, w1, a1[2]);
                a0[3] = fma2(xc.y, w0, a0[3]); a1[3] = fma2(xc.y, w1, a1[3]);
            }
        }
        __syncthreads();
        if (has_next) {
#pragma unroll
            for (int i = 0; i < 4; i++)
                xs[lf * XSS + mh * 4 + i] = pack2(xv[2 * i], xv[2 * i + 1]);
        }
        __syncthreads();
    }

    // ---- store partial [16 tokens x 2 cols] ----
    float* dst = g_part[z] + (size_t)e * MT * FF + f;
    const int mt0 = mh * 8;
#pragma unroll
    for (int j = 0; j < 4; j++) {
        float2 v0 = unpk(a0[j]);   // (m_lo, m_hi) at col f
        float2 v1 = unpk(a1[j]);   // at col f+1
        const int m_lo = mt0 + 2 * j, m_hi = m_lo + 1;
        *(float2*)(dst + (size_t)m_lo * FF) = make_float2(v0.x, v1.x);
        *(float2*)(dst + (size_t)m_hi * FF) = make_float2(v0.y, v1.y);
    }
}

// ============================================================================
// K2 fuse: inter = silu(p00+p01) * (p10+p11), elementwise float4.
// g_part layout: z = wm*2 + zk  ->  gate halves are z=0,1; up halves z=2,3.
// ============================================================================
__global__ __launch_bounds__(256, 8)
void moe_fuse_kernel() {
    const size_t i = (size_t)blockIdx.x * 256 + threadIdx.x;   // float4 index
    const float4 g0 = ((const float4*)g_part[0])[i];
    const float4 g1 = ((const float4*)g_part[1])[i];
    const float4 u0 = ((const float4*)g_part[2])[i];
    const float4 u1 = ((const float4*)g_part[3])[i];
    float4 r;
    r.x = silu(g0.x + g1.x) * (u0.x + u1.x);
    r.y = silu(g0.y + g1.y) * (u0.y + u1.y);
    r.z = silu(g0.z + g1.z) * (u0.z + u1.z);
    r.w = silu(g0.w + g1.w) * (u0.w + u1.w);
    ((float4*)g_inter)[i] = r;
}

// ============================================================================
// K3 down: opart[zk][e,m,h] = inter_e[:, kr] @ down_e[kr, h], kr = zk-th half
// Grid: (HH/128, NE, 2). Same R3-B pipeline, 2048 CTAs -> 8/SM, 32 warps.
// ============================================================================
__global__ __launch_bounds__(128, 8)
void moe_down_kernel(const float* __restrict__ down) {
    const int e   = blockIdx.y;
    const int zk  = blockIdx.z;           // k-half: [zk*704, zk*704+704)
    const int tid = threadIdx.x;
    const int lf  = tid & 63;
    const int mh  = tid >> 6;
    const int h   = blockIdx.x * 128 + lf * 2;
    const int KH  = FF / 2;               // 704 = 11 * KT

    __shared__ ull xs[KT * XSS];

    ull a0[4], a1[4];
#pragma unroll
    for (int j = 0; j < 4; j++) { a0[j] = 0; a1[j] = 0; }

    const float* ib = g_inter + (size_t)e * MT * FF + (size_t)zk * KH;
    float xv[8];

#pragma unroll
    for (int i = 0; i < 4; i++) {
        int m0 = (mh * 4 + i) * 2;
        xv[2 * i]     = ib[(size_t)m0 * FF + lf];
        xv[2 * i + 1] = ib[(size_t)(m0 + 1) * FF + lf];
    }
#pragma unroll
    for (int i = 0; i < 4; i++)
        xs[lf * XSS + mh * 4 + i] = pack2(xv[2 * i], xv[2 * i + 1]);
    __syncthreads();

    const float* dp0 = down + ((size_t)e * FF + zk * KH) * HH + h;

    for (int k0 = 0; k0 < KH; k0 += KT) {
        const bool has_next = (k0 + KT < KH);
        if (has_next) {
#pragma unroll
            for (int i = 0; i < 4; i++) {
                int m0 = (mh * 4 + i) * 2;
                xv[2 * i]     = ib[(size_t)m0 * FF + k0 + KT + lf];
                xv[2 * i + 1] = ib[(size_t)(m0 + 1) * FF + k0 + KT + lf];
            }
        }

        const float* dp = dp0 + (size_t)k0 * HH;

        float2 wd[2][4];
#pragma unroll
        for (int j = 0; j < 4; j++)
            wd[0][j] = *(const float2*)(dp + (size_t)j * HH);
#pragma unroll 4
        for (int kg = 0; kg < KT / 4; kg++) {
            const int cur = kg & 1, nxt = cur ^ 1;
            if (kg < KT / 4 - 1) {
#pragma unroll
                for (int j = 0; j < 4; j++)
                    wd[nxt][j] = *(const float2*)(dp + (size_t)(4 * kg + 4 + j) * HH);
            }
#pragma unroll
            for (int j = 0; j < 4; j++) {
                const int k = kg * 4 + j;
                ull w0 = dup2(wd[cur][j].x), w1 = dup2(wd[cur][j].y);
                const ulonglong2* xr = (const ulonglong2*)&xs[k * XSS + mh * 4];
                ulonglong2 xa = xr[0];
                ulonglong2 xc = xr[1];
                a0[0] = fma2(xa.x, w0, a0[0]); a1[0] = fma2(xa.x, w1, a1[0]);
                a0[1] = fma2(xa.y, w0, a0[1]); a1[1] = fma2(xa.y, w1, a1[1]);
                a0[2] = fma2(xc.x, w0, a0[2]); a1[2] = fma2(xc.x, w1, a1[2]);
                a0[3] = fma2(xc.y, w0, a0[3]); a1[3] = fma2(xc.y, w1, a1[3]);
            }
        }
        __syncthreads();
        if (has_next) {
#pragma unroll
            for (int i = 0; i < 4; i++)
                xs[lf * XSS + mh * 4 + i] = pack2(xv[2 * i], xv[2 * i + 1]);
        }
        __syncthreads();
    }

    float* ob = g_opart[zk] + (size_t)e * MT * HH + h;
    const int mt0 = mh * 8;
#pragma unroll
    for (int j = 0; j < 4; j++) {
        float2 v0 = unpk(a0[j]);
        float2 v1 = unpk(a1[j]);
        const int m_lo = mt0 + 2 * j, m_hi = m_lo + 1;
        *(float2*)(ob + (size_t)m_lo * HH) = make_float2(v0.x, v1.x);
        *(float2*)(ob + (size_t)m_hi * HH) = make_float2(v0.y, v1.y);
    }
}

// ============================================================================
// K4 combine: out = q0 + q1, elementwise float4.
// ============================================================================
__global__ __launch_bounds__(256, 8)
void moe_combine_kernel(float* __restrict__ out) {
    const size_t i = (size_t)blockIdx.x * 256 + threadIdx.x;   // float4 index
    const float4 q0 = ((const float4*)g_opart[0])[i];
    const float4 q1 = ((const float4*)g_opart[1])[i];
    ((float4*)out)[i] = make_float4(q0.x + q1.x, q0.y + q1.y,
                                    q0.z + q1.z, q0.w + q1.w);
}

// ============================================================================
// Launch
// Inputs (metadata order):
//   d_in[0] = permuted_local_hidden_states [T=1024, H=2048] f32
//   d_in[1] = gate_proj [E, H, F] f32
//   d_in[2] = up_proj   [E, H, F] f32
//   d_in[3] = down_proj [E, F, H] f32
//   d_in[4] = tokens_per_expert [E] i32  (uniform 16 — unused)
// Output: [T, H] f32
// ============================================================================
extern "C" void kernel_launch(void* const* d_in, const int* in_sizes, int n_in,
                              void* d_out, int out_size) {
    const float* x    = (const float*)d_in[0];
    const float* gate = (const float*)d_in[1];
    const float* up   = (const float*)d_in[2];
    const float* down = (const float*)d_in[3];
    float* out = (float*)d_out;

    dim3 g1(FF / 128, NE, 4);     // 2816 CTAs
    moe_proj_kernel<<<g1, 128>>>(x, gate, up);

    // NE*MT*FF/4 float4s / 256 threads = 1408 blocks (exact)
    moe_fuse_kernel<<<(NE * MT * FF / 4) / 256, 256>>>();

    dim3 g3(HH / 128, NE, 2);     // 2048 CTAs
    moe_down_kernel<<<g3, 128>>>(down);

    // NE*MT*HH/4 float4s / 256 threads = 2048 blocks (exact)
    moe_combine_kernel<<<(NE * MT * HH / 4) / 256, 256>>>(out);
}